// round 13
// baseline (speedup 1.0000x reference)
#include <cuda_runtime.h>

#define B 64
#define CIN 512
#define HIDE 128
#define OP 512
#define HW 4096   // 64*64

// scratch for pooled y [B, CIN]
__device__ float g_y[B * CIN];

__device__ __forceinline__ void prefetch_l2(const void* p) {
    asm volatile("prefetch.global.L2 [%0];" :: "l"(p));
}

// ---------------------------------------------------------------------------
// Kernel 1: global average pool — EXACT proven body (87.6% DRAM).
// ---------------------------------------------------------------------------
__global__ __launch_bounds__(256) void pool_kernel(const float* __restrict__ x,
                                                   float* __restrict__ y) {
    cudaTriggerProgrammaticLaunchCompletion();

    const int row = blockIdx.x;
    const float4* p = reinterpret_cast<const float4*>(x + (size_t)row * HW);
    const int t = threadIdx.x;

    float s = 0.0f;
#pragma unroll
    for (int i = 0; i < 4; i++) {
        float4 v = __ldcs(&p[t + i * 256]);
        s += (v.x + v.y) + (v.z + v.w);
    }
#pragma unroll
    for (int o = 16; o > 0; o >>= 1) s += __shfl_xor_sync(0xFFFFFFFFu, s, o);

    __shared__ float sm[8];
    if ((t & 31) == 0) sm[t >> 5] = s;
    __syncthreads();
    if (t < 8) {
        float v = sm[t];
#pragma unroll
        for (int o = 4; o > 0; o >>= 1) v += __shfl_xor_sync(0x000000FFu, v, o);
        if (t == 0) y[row] = v * (1.0f / (float)HW);
    }
}

// ---------------------------------------------------------------------------
// Kernel 2: fused AGCA head — TWO serial memory rounds.
// Round 1: y + W1 + A2 loads all batched (A2 preloaded to registers).
// Round 2: W4 (L2-warm from pre-sync prefetch).
// One block per batch, 1024 threads, PDL.
// ---------------------------------------------------------------------------
__global__ __launch_bounds__(1024) void head_kernel(const float* __restrict__ y,
                                                    const float* __restrict__ W1,
                                                    const float* __restrict__ A2,
                                                    const float* __restrict__ w2p,
                                                    const float* __restrict__ w3p,
                                                    const float* __restrict__ W4,
                                                    float* __restrict__ out) {
    const int b    = blockIdx.x;
    const int tid  = threadIdx.x;
    const int wid  = tid >> 5;
    const int lane = tid & 31;

    // ---- L2 prefetch of this block's 1/64 slice of the weights (pre-sync) ----
    {
        const char* w1c = (const char*)W1;
        const char* w4c = (const char*)W4;
        const char* a2c = (const char*)A2;
        if (tid < 32) {
            prefetch_l2(w1c + ((size_t)b * 32 + tid) * 128);
        } else if (tid < 64) {
            prefetch_l2(w4c + ((size_t)b * 32 + (tid - 32)) * 128);
        } else if (tid < 72) {
            prefetch_l2(a2c + ((size_t)b * 8 + (tid - 64)) * 128);
        }
    }

    cudaGridDependencySynchronize();

    __shared__ float y1s[HIDE];
    __shared__ float a1s[HIDE];
    __shared__ float y3s[HIDE];
    __shared__ float part[8][HIDE];   // A2 partial sums
    __shared__ float red[8];

    // ---- A2 preload (independent of data): thread (h=tid&127, s=tid>>7)
    //      owns j in [16s, 16s+16) ----
    const int hA = tid & (HIDE - 1);
    const int sA = tid >> 7;
    const int j0 = sA << 4;
    float a2r[16];
#pragma unroll
    for (int j = 0; j < 16; j++)
        a2r[j] = __ldg(&A2[(j0 + j) * HIDE + hA]);

    // ---- GEMV1: warp wid -> h = wid*4 + {0..3}; y read direct from L2,
    //      batched with W1 (round 1) ----
    {
        const int h0 = wid << 2;
        const float* yb = y + b * CIN;
        const float* r0 = W1 + (size_t)(h0 + 0) * CIN;
        const float* r1 = W1 + (size_t)(h0 + 1) * CIN;
        const float* r2 = W1 + (size_t)(h0 + 2) * CIN;
        const float* r3 = W1 + (size_t)(h0 + 3) * CIN;
        float a0 = 0.f, a1 = 0.f, a2 = 0.f, a3 = 0.f;
#pragma unroll
        for (int k = 0; k < CIN / 32; k++) {
            const int c = lane + (k << 5);
            const float yv = __ldg(yb + c);
            a0 += yv * __ldg(r0 + c);
            a1 += yv * __ldg(r1 + c);
            a2 += yv * __ldg(r2 + c);
            a3 += yv * __ldg(r3 + c);
        }
#pragma unroll
        for (int o = 16; o > 0; o >>= 1) {
            a0 += __shfl_xor_sync(0xFFFFFFFFu, a0, o);
            a1 += __shfl_xor_sync(0xFFFFFFFFu, a1, o);
            a2 += __shfl_xor_sync(0xFFFFFFFFu, a2, o);
            a3 += __shfl_xor_sync(0xFFFFFFFFu, a3, o);
        }
        if (lane == 0) {
            y1s[h0 + 0] = a0; y1s[h0 + 1] = a1;
            y1s[h0 + 2] = a2; y1s[h0 + 3] = a3;
        }
    }
    __syncthreads();

    // ---- A2 partials: pure FMA (weights already in registers) ----
    {
        float t = 0.0f;
#pragma unroll
        for (int j = 0; j < 16; j++)
            t += y1s[j0 + j] * a2r[j];
        part[sA][hA] = t;
    }

    // ---- softmax(w2 * y1) over 128 channels (warps 0..3) ----
    const float w2 = __ldg(w2p);
    if (tid < HIDE) {
        const float z = w2 * y1s[tid];
        float m = z;
#pragma unroll
        for (int o = 16; o > 0; o >>= 1) m = fmaxf(m, __shfl_xor_sync(0xFFFFFFFFu, m, o));
        if (lane == 0) red[wid] = m;
    }
    __syncthreads();
    if (tid < HIDE) {
        const float m = fmaxf(fmaxf(red[0], red[1]), fmaxf(red[2], red[3]));
        const float e = expf(w2 * y1s[tid] - m);
        a1s[tid] = e;
        float ssum = e;
#pragma unroll
        for (int o = 16; o > 0; o >>= 1) ssum += __shfl_xor_sync(0xFFFFFFFFu, ssum, o);
        if (lane == 0) red[4 + wid] = ssum;
    }
    __syncthreads();

    // ---- combine: y3[h] = relu(w3 * (y1*a1 + sum_s part[s][h])) ----
    if (tid < HIDE) {
        const float ssum = (red[4] + red[5]) + (red[6] + red[7]);
        const float a1n = a1s[tid] / ssum;
        float t = y1s[tid] * a1n;
        float p0 = part[0][tid] + part[1][tid];
        float p1 = part[2][tid] + part[3][tid];
        float p2 = part[4][tid] + part[5][tid];
        float p3 = part[6][tid] + part[7][tid];
        t += (p0 + p1) + (p2 + p3);
        const float w3 = __ldg(w3p);
        y3s[tid] = fmaxf(w3 * t, 0.0f);
    }
    __syncthreads();

    // ---- GEMV4: warp wid owns 16 outputs, single pass (round 2, L2-warm) ----
    {
        const int o_base = wid << 4;
        float acc[16];
#pragma unroll
        for (int i = 0; i < 16; i++) acc[i] = 0.0f;
#pragma unroll
        for (int k = 0; k < HIDE / 32; k++) {
            const int j = lane + (k << 5);
            const float yv = y3s[j];
#pragma unroll
            for (int i = 0; i < 16; i++)
                acc[i] += yv * __ldg(&W4[(size_t)(o_base + i) * HIDE + j]);
        }
#pragma unroll
        for (int off = 16; off > 0; off >>= 1) {
#pragma unroll
            for (int i = 0; i < 16; i++)
                acc[i] += __shfl_xor_sync(0xFFFFFFFFu, acc[i], off);
        }
        if (lane == 0) {
#pragma unroll
            for (int i = 0; i < 16; i++)
                out[b * OP + o_base + i] = 1.0f / (1.0f + expf(-acc[i]));
        }
    }
}

extern "C" void kernel_launch(void* const* d_in, const int* in_sizes, int n_in,
                              void* d_out, int out_size) {
    const float* x  = (const float*)d_in[0];
    const float* W1 = (const float*)d_in[1];
    const float* A2 = (const float*)d_in[2];
    const float* w2 = (const float*)d_in[3];
    const float* w3 = (const float*)d_in[4];
    const float* W4 = (const float*)d_in[5];
    float* out = (float*)d_out;

    float* yscratch;
    cudaGetSymbolAddress((void**)&yscratch, g_y);

    pool_kernel<<<B * CIN, 256>>>(x, yscratch);

    cudaLaunchConfig_t cfg = {};
    cfg.gridDim = dim3(B);
    cfg.blockDim = dim3(1024);
    cfg.dynamicSmemBytes = 0;
    cfg.stream = 0;
    cudaLaunchAttribute attr[1];
    attr[0].id = cudaLaunchAttributeProgrammaticStreamSerialization;
    attr[0].val.programmaticStreamSerializationAllowed = 1;
    cfg.attrs = attr;
    cfg.numAttrs = 1;
    cudaLaunchKernelEx(&cfg, head_kernel, (const float*)yscratch, W1, A2, w2, w3, W4, out);
}

// round 14
// speedup vs baseline: 1.0082x; 1.0082x over previous
#include <cuda_runtime.h>

#define B 64
#define CIN 512
#define HIDE 128
#define OP 512
#define HW 4096   // 64*64

// scratch for pooled y [B, CIN]
__device__ float g_y[B * CIN];

__device__ __forceinline__ void prefetch_l2(const void* p) {
    asm volatile("prefetch.global.L2 [%0];" :: "l"(p));
}

// ---------------------------------------------------------------------------
// Kernel 1: global average pool — EXACT proven body (87.6% DRAM).
// ---------------------------------------------------------------------------
__global__ __launch_bounds__(256) void pool_kernel(const float* __restrict__ x,
                                                   float* __restrict__ y) {
    cudaTriggerProgrammaticLaunchCompletion();

    const int row = blockIdx.x;
    const float4* p = reinterpret_cast<const float4*>(x + (size_t)row * HW);
    const int t = threadIdx.x;

    float s = 0.0f;
#pragma unroll
    for (int i = 0; i < 4; i++) {
        float4 v = __ldcs(&p[t + i * 256]);
        s += (v.x + v.y) + (v.z + v.w);
    }
#pragma unroll
    for (int o = 16; o > 0; o >>= 1) s += __shfl_xor_sync(0xFFFFFFFFu, s, o);

    __shared__ float sm[8];
    if ((t & 31) == 0) sm[t >> 5] = s;
    __syncthreads();
    if (t < 8) {
        float v = sm[t];
#pragma unroll
        for (int o = 4; o > 0; o >>= 1) v += __shfl_xor_sync(0x000000FFu, v, o);
        if (t == 0) y[row] = v * (1.0f / (float)HW);
    }
}

// ---------------------------------------------------------------------------
// Kernel 2: fused AGCA head (R12 structure). Weight fetches hoisted PRE-sync:
// A2 into registers, W1/W4 prefetched into L2 — all complete during the
// pool's drain. Post-sync path touches memory only for y (L2) + warm weights.
// One block per batch, 1024 threads, PDL.
// ---------------------------------------------------------------------------
__global__ __launch_bounds__(1024) void head_kernel(const float* __restrict__ y,
                                                    const float* __restrict__ W1,
                                                    const float* __restrict__ A2,
                                                    const float* __restrict__ w2p,
                                                    const float* __restrict__ w3p,
                                                    const float* __restrict__ W4,
                                                    float* __restrict__ out) {
    const int b    = blockIdx.x;
    const int tid  = threadIdx.x;
    const int wid  = tid >> 5;
    const int lane = tid & 31;

    // ---- PRE-SYNC: L2 prefetch of this block's 1/64 slice of W1/W4 ----
    {
        const char* w1c = (const char*)W1;
        const char* w4c = (const char*)W4;
        if (tid < 32) {
            prefetch_l2(w1c + ((size_t)b * 32 + tid) * 128);
        } else if (tid < 64) {
            prefetch_l2(w4c + ((size_t)b * 32 + (tid - 32)) * 128);
        }
    }

    // ---- PRE-SYNC: A2 preload into registers (A2 is a stable input).
    //      thread (h = tid&127, slice s = tid>>7) owns j in [16s, 16s+16) ----
    const int hA = tid & (HIDE - 1);
    const int sA = tid >> 7;
    const int j0 = sA << 4;
    float a2r[16];
#pragma unroll
    for (int j = 0; j < 16; j++)
        a2r[j] = __ldg(&A2[(j0 + j) * HIDE + hA]);

    // scalars are stable inputs too
    const float w2 = __ldg(w2p);
    const float w3 = __ldg(w3p);

    cudaGridDependencySynchronize();

    __shared__ float ys[CIN];
    __shared__ float y1s[HIDE];
    __shared__ float a1s[HIDE];
    __shared__ float y3s[HIDE];
    __shared__ float part[8][HIDE];
    __shared__ float red[8];

    if (tid < CIN) ys[tid] = y[b * CIN + tid];
    __syncthreads();

    // ---- GEMV1: warp wid -> h = wid*4 + {0..3}; 64 batched loads (L2-warm) ----
    {
        const int h0 = wid << 2;
        const float* r0 = W1 + (size_t)(h0 + 0) * CIN;
        const float* r1 = W1 + (size_t)(h0 + 1) * CIN;
        const float* r2 = W1 + (size_t)(h0 + 2) * CIN;
        const float* r3 = W1 + (size_t)(h0 + 3) * CIN;
        float a0 = 0.f, a1 = 0.f, a2 = 0.f, a3 = 0.f;
#pragma unroll
        for (int k = 0; k < CIN / 32; k++) {
            const int c = lane + (k << 5);
            const float yv = ys[c];
            a0 += yv * __ldg(r0 + c);
            a1 += yv * __ldg(r1 + c);
            a2 += yv * __ldg(r2 + c);
            a3 += yv * __ldg(r3 + c);
        }
#pragma unroll
        for (int o = 16; o > 0; o >>= 1) {
            a0 += __shfl_xor_sync(0xFFFFFFFFu, a0, o);
            a1 += __shfl_xor_sync(0xFFFFFFFFu, a1, o);
            a2 += __shfl_xor_sync(0xFFFFFFFFu, a2, o);
            a3 += __shfl_xor_sync(0xFFFFFFFFu, a3, o);
        }
        if (lane == 0) {
            y1s[h0 + 0] = a0; y1s[h0 + 1] = a1;
            y1s[h0 + 2] = a2; y1s[h0 + 3] = a3;
        }
    }
    __syncthreads();

    // ---- A2 partials: pure FMA (weights already in registers) ----
    {
        float t = 0.0f;
#pragma unroll
        for (int j = 0; j < 16; j++)
            t += y1s[j0 + j] * a2r[j];
        part[sA][hA] = t;
    }

    // ---- softmax(w2 * y1) over 128 channels (warps 0..3) ----
    if (tid < HIDE) {
        const float z = w2 * y1s[tid];
        float m = z;
#pragma unroll
        for (int o = 16; o > 0; o >>= 1) m = fmaxf(m, __shfl_xor_sync(0xFFFFFFFFu, m, o));
        if (lane == 0) red[wid] = m;
    }
    __syncthreads();
    if (tid < HIDE) {
        const float m = fmaxf(fmaxf(red[0], red[1]), fmaxf(red[2], red[3]));
        const float e = expf(w2 * y1s[tid] - m);
        a1s[tid] = e;
        float ssum = e;
#pragma unroll
        for (int o = 16; o > 0; o >>= 1) ssum += __shfl_xor_sync(0xFFFFFFFFu, ssum, o);
        if (lane == 0) red[4 + wid] = ssum;
    }
    __syncthreads();

    // ---- combine: y3[h] = relu(w3 * (y1*a1 + sum_s part[s][h])) ----
    if (tid < HIDE) {
        const float ssum = (red[4] + red[5]) + (red[6] + red[7]);
        const float a1n = a1s[tid] / ssum;
        float t = y1s[tid] * a1n;
        float p0 = part[0][tid] + part[1][tid];
        float p1 = part[2][tid] + part[3][tid];
        float p2 = part[4][tid] + part[5][tid];
        float p3 = part[6][tid] + part[7][tid];
        t += (p0 + p1) + (p2 + p3);
        y3s[tid] = fmaxf(w3 * t, 0.0f);
    }
    __syncthreads();

    // ---- GEMV4: warp wid owns 16 outputs, single pass (L2-warm) ----
    {
        const int o_base = wid << 4;
        float acc[16];
#pragma unroll
        for (int i = 0; i < 16; i++) acc[i] = 0.0f;
#pragma unroll
        for (int k = 0; k < HIDE / 32; k++) {
            const int j = lane + (k << 5);
            const float yv = y3s[j];
#pragma unroll
            for (int i = 0; i < 16; i++)
                acc[i] += yv * __ldg(&W4[(size_t)(o_base + i) * HIDE + j]);
        }
#pragma unroll
        for (int off = 16; off > 0; off >>= 1) {
#pragma unroll
            for (int i = 0; i < 16; i++)
                acc[i] += __shfl_xor_sync(0xFFFFFFFFu, acc[i], off);
        }
        if (lane == 0) {
#pragma unroll
            for (int i = 0; i < 16; i++)
                out[b * OP + o_base + i] = 1.0f / (1.0f + expf(-acc[i]));
        }
    }
}

extern "C" void kernel_launch(void* const* d_in, const int* in_sizes, int n_in,
                              void* d_out, int out_size) {
    const float* x  = (const float*)d_in[0];
    const float* W1 = (const float*)d_in[1];
    const float* A2 = (const float*)d_in[2];
    const float* w2 = (const float*)d_in[3];
    const float* w3 = (const float*)d_in[4];
    const float* W4 = (const float*)d_in[5];
    float* out = (float*)d_out;

    float* yscratch;
    cudaGetSymbolAddress((void**)&yscratch, g_y);

    pool_kernel<<<B * CIN, 256>>>(x, yscratch);

    cudaLaunchConfig_t cfg = {};
    cfg.gridDim = dim3(B);
    cfg.blockDim = dim3(1024);
    cfg.dynamicSmemBytes = 0;
    cfg.stream = 0;
    cudaLaunchAttribute attr[1];
    attr[0].id = cudaLaunchAttributeProgrammaticStreamSerialization;
    attr[0].val.programmaticStreamSerializationAllowed = 1;
    cfg.attrs = attr;
    cfg.numAttrs = 1;
    cudaLaunchKernelEx(&cfg, head_kernel, (const float*)yscratch, W1, A2, w2, w3, W4, out);
}